// round 9
// baseline (speedup 1.0000x reference)
#include <cuda_runtime.h>
#include <cstdint>

// Fixed geometry: x_list (P=16384, N=1024, 2) float32, scale scalar.
// segn = N/4 = 256 segments per row; segment i uses points 3i..3i+3.
#define N_POINTS   1024
#define SEGN       256
#define NSLOTS     128

// Each slot on its own 128B line: value-atomics and counter-atomics for a
// slot share a line (fine — same LTS ALU handles ~256 spread-in-time ops),
// but distinct slots never collide in the LTS hash.
struct __align__(128) Slot {
    float        v;
    unsigned int c;
    char         pad[120];
};
__device__ Slot         g_slot[NSLOTS];    // zero-init at module load
__device__ unsigned int g_master = 0;

// Crossing term for one segment given its 4 points.
__device__ __forceinline__ float seg_term(float2 p0, float2 p1, float2 p2, float2 p3)
{
    const float v1x = p1.x - p0.x, v1y = p1.y - p0.y;
    const float v2x = p2.x - p1.x, v2y = p2.y - p1.y;
    const float v3x = p3.x - p2.x, v3y = p3.y - p2.y;

    // direct = (s12 >= 0) depends only on sign of cross(v1,v2):
    // the positive norm product cannot flip the sign.
    const float c12 = v1x * v2y - v1y * v2x;
    const float c13 = v1x * v3y - v1y * v3x;

    const float n2   = (v1x * v1x + v1y * v1y) * (v3x * v3x + v3y * v3y);
    const float sina = c13 * rsqrtf(n2);

    return (c12 >= 0.0f) ? fmaxf(-sina, 0.0f) : fmaxf(sina, 0.0f);
}

__global__ void __launch_bounds__(SEGN, 8) xing_kernel(
    const float* __restrict__ x,
    const uint32_t* __restrict__ scale_raw,
    float* __restrict__ out, int P, int nblocks)
{
    const int t = threadIdx.x;               // segment index 0..255

    // One row per block; segment t starts at point 3t.
    const float2* __restrict__ p =
        reinterpret_cast<const float2*>(x)
        + (size_t)blockIdx.x * N_POINTS + 3 * t;

    const float2 p0 = __ldg(p + 0);
    const float2 p1 = __ldg(p + 1);
    const float2 p2 = __ldg(p + 2);
    const float2 p3 = __ldg(p + 3);
    float acc = seg_term(p0, p1, p2, p3);

    // ---- block reduce ----
    #pragma unroll
    for (int o = 16; o > 0; o >>= 1)
        acc += __shfl_down_sync(0xFFFFFFFFu, acc, o);

    __shared__ float s[SEGN / 32];
    if ((t & 31) == 0) s[t >> 5] = acc;
    __syncthreads();

    // Thread 0 only; all other threads/blocks exit immediately.
    if (t == 0) {
        float bs = 0.0f;
        #pragma unroll
        for (int i = 0; i < SEGN / 32; i++) bs += s[i];

        const int per_slot = nblocks / NSLOTS;          // 128
        const int sid      = blockIdx.x & (NSLOTS - 1);

        atomicAdd(&g_slot[sid].v, bs);
        __threadfence();
        unsigned int d = atomicAdd(&g_slot[sid].c, 1u);

        if (d == (unsigned int)(per_slot - 1)) {
            // Last arriver in this slot group.
            atomicExch(&g_slot[sid].c, 0u);             // reset for replay
            __threadfence();
            unsigned int m = atomicAdd(&g_master, 1u);

            if (m == NSLOTS - 1) {
                // All slot groups complete (fences make all v-adds visible).
                float total = 0.0f;
                #pragma unroll
                for (int i = 0; i < NSLOTS; i++)
                    total += __ldcg(&g_slot[i].v);
                #pragma unroll
                for (int i = 0; i < NSLOTS; i++)
                    g_slot[i].v = 0.0f;                  // reset for replay

                // Decode scale: float32 bit pattern vs integer bit pattern.
                uint32_t u = scale_raw[0];
                float    f = __uint_as_float(u);
                float    scale;
                if (fabsf(f) >= 1e-30f && fabsf(f) < 1e30f) scale = f;
                else                                        scale = (float)(int)u;

                out[0] = total * scale / ((float)SEGN * (float)P);
                atomicExch(&g_master, 0u);               // reset for replay
            }
        }
    }
}

extern "C" void kernel_launch(void* const* d_in, const int* in_sizes, int n_in,
                              void* d_out, int out_size)
{
    const float*    x     = (const float*)d_in[0];
    const uint32_t* scale = (const uint32_t*)d_in[1];
    float*          out   = (float*)d_out;

    int P = in_sizes[0] / (N_POINTS * 2);     // 16384

    xing_kernel<<<P, SEGN>>>(x, scale, out, P, P);
}

// round 10
// speedup vs baseline: 1.5917x; 1.5917x over previous
#include <cuda_runtime.h>
#include <cstdint>

// Fixed geometry: x_list (P=16384, N=1024, 2) float32, scale scalar.
// segn = N/4 = 256 segments per row; segment i uses points 3i..3i+3.
#define N_POINTS        1024
#define SEGN            256
#define ROWS_PER_BLOCK  4
#define NSLOTS          32

__device__ float        g_slots[NSLOTS];   // zero-init at load; reset each launch
__device__ unsigned int g_counter = 0;

// Crossing term for one segment given its 4 points.
__device__ __forceinline__ float seg_term(float2 p0, float2 p1, float2 p2, float2 p3)
{
    const float v1x = p1.x - p0.x, v1y = p1.y - p0.y;
    const float v2x = p2.x - p1.x, v2y = p2.y - p1.y;
    const float v3x = p3.x - p2.x, v3y = p3.y - p2.y;

    // direct = (s12 >= 0) depends only on sign of cross(v1,v2):
    // the positive norm product cannot flip the sign.
    const float c12 = v1x * v2y - v1y * v2x;
    const float c13 = v1x * v3y - v1y * v3x;

    const float n2   = (v1x * v1x + v1y * v1y) * (v3x * v3x + v3y * v3y);
    const float sina = c13 * rsqrtf(n2);

    return (c12 >= 0.0f) ? fmaxf(-sina, 0.0f) : fmaxf(sina, 0.0f);
}

__global__ void __launch_bounds__(SEGN, 8) xing_kernel(
    const float* __restrict__ x,
    const uint32_t* __restrict__ scale_raw,
    float* __restrict__ out, int P, int nblocks)
{
    const int t = threadIdx.x;               // segment index 0..255

    // Segment t starts at point 3t within each row.
    const float2* __restrict__ base =
        reinterpret_cast<const float2*>(x)
        + (size_t)blockIdx.x * ROWS_PER_BLOCK * N_POINTS + 3 * t;

    float acc = 0.0f;

    #pragma unroll
    for (int r = 0; r < ROWS_PER_BLOCK; r++) {
        const float2* p = base + (size_t)r * N_POINTS;
        const float2 p0 = __ldg(p + 0);
        const float2 p1 = __ldg(p + 1);
        const float2 p2 = __ldg(p + 2);
        const float2 p3 = __ldg(p + 3);
        acc += seg_term(p0, p1, p2, p3);
    }

    // ---- block reduce ----
    #pragma unroll
    for (int o = 16; o > 0; o >>= 1)
        acc += __shfl_down_sync(0xFFFFFFFFu, acc, o);

    __shared__ float s[SEGN / 32];
    if ((t & 31) == 0) s[t >> 5] = acc;
    __syncthreads();

    // Thread 0 only: accumulate into spread slots, detect last block, finalize.
    // Other threads (and other blocks) exit immediately — no extra barrier.
    if (t == 0) {
        float bs = 0.0f;
        #pragma unroll
        for (int i = 0; i < SEGN / 32; i++) bs += s[i];

        // 32 distinct L2 addresses, ~128 adds each, spread over the kernel
        // lifetime -> negligible atomic contention.
        atomicAdd(&g_slots[blockIdx.x & (NSLOTS - 1)], bs);
        __threadfence();
        unsigned int done = atomicAdd(&g_counter, 1u);

        if (done == (unsigned int)(nblocks - 1)) {
            // Last block: fold the 32 slots (32 independent loads, one
            // latency exposure) and reset state for the next graph replay.
            float v[NSLOTS];
            #pragma unroll
            for (int i = 0; i < NSLOTS; i++) v[i] = __ldcg(&g_slots[i]);

            float total = 0.0f;
            #pragma unroll
            for (int i = 0; i < NSLOTS; i++) {
                total += v[i];
                g_slots[i] = 0.0f;
            }

            // Decode scale: float32 bit pattern vs integer bit pattern.
            uint32_t u = scale_raw[0];
            float    f = __uint_as_float(u);
            float    scale;
            if (fabsf(f) >= 1e-30f && fabsf(f) < 1e30f) scale = f;
            else                                        scale = (float)(int)u;

            out[0] = total * scale / ((float)SEGN * (float)P);
            atomicExch(&g_counter, 0u);       // reset for next replay
        }
    }
}

extern "C" void kernel_launch(void* const* d_in, const int* in_sizes, int n_in,
                              void* d_out, int out_size)
{
    const float*    x     = (const float*)d_in[0];
    const uint32_t* scale = (const uint32_t*)d_in[1];
    float*          out   = (float*)d_out;

    int P       = in_sizes[0] / (N_POINTS * 2);     // 16384
    int nblocks = P / ROWS_PER_BLOCK;               // 4096

    xing_kernel<<<nblocks, SEGN>>>(x, scale, out, P, nblocks);
}

// round 11
// speedup vs baseline: 1.7164x; 1.0784x over previous
#include <cuda_runtime.h>
#include <cstdint>

// Fixed geometry: x_list (P=16384, N=1024, 2) float32, scale scalar.
// segn = N/4 = 256 segments per row; segment i uses points 3i..3i+3.
#define N_POINTS        1024
#define SEGN            256
#define ROWS_PER_BLOCK  8
#define NSLOTS          32

__device__ float        g_slots[NSLOTS];   // zero-init at load; reset each launch
__device__ unsigned int g_counter = 0;

// Read-only 64-bit load with 256B L2 fetch-granule promotion: the per-warp
// stream is 768B contiguous, so paired-sector DRAM fetches are always useful.
__device__ __forceinline__ float2 ldg2_l2_256(const float2* p)
{
    float2 r;
    asm volatile("ld.global.nc.L2::256B.v2.f32 {%0, %1}, [%2];"
                 : "=f"(r.x), "=f"(r.y) : "l"(p));
    return r;
}

// Crossing term for one segment given its 4 points.
__device__ __forceinline__ float seg_term(float2 p0, float2 p1, float2 p2, float2 p3)
{
    const float v1x = p1.x - p0.x, v1y = p1.y - p0.y;
    const float v2x = p2.x - p1.x, v2y = p2.y - p1.y;
    const float v3x = p3.x - p2.x, v3y = p3.y - p2.y;

    // direct = (s12 >= 0) depends only on sign of cross(v1,v2):
    // the positive norm product cannot flip the sign.
    const float c12 = v1x * v2y - v1y * v2x;
    const float c13 = v1x * v3y - v1y * v3x;

    const float n2   = (v1x * v1x + v1y * v1y) * (v3x * v3x + v3y * v3y);
    const float sina = c13 * rsqrtf(n2);

    return (c12 >= 0.0f) ? fmaxf(-sina, 0.0f) : fmaxf(sina, 0.0f);
}

__global__ void __launch_bounds__(SEGN, 8) xing_kernel(
    const float* __restrict__ x,
    const uint32_t* __restrict__ scale_raw,
    float* __restrict__ out, int P, int nblocks)
{
    const int t = threadIdx.x;               // segment index 0..255

    // Segment t starts at point 3t within each row.
    const float2* __restrict__ base =
        reinterpret_cast<const float2*>(x)
        + (size_t)blockIdx.x * ROWS_PER_BLOCK * N_POINTS + 3 * t;

    float acc = 0.0f;

    #pragma unroll
    for (int r = 0; r < ROWS_PER_BLOCK; r++) {
        const float2* p = base + (size_t)r * N_POINTS;
        const float2 p0 = ldg2_l2_256(p + 0);
        const float2 p1 = ldg2_l2_256(p + 1);
        const float2 p2 = ldg2_l2_256(p + 2);
        const float2 p3 = ldg2_l2_256(p + 3);
        acc += seg_term(p0, p1, p2, p3);
    }

    // ---- block reduce ----
    #pragma unroll
    for (int o = 16; o > 0; o >>= 1)
        acc += __shfl_down_sync(0xFFFFFFFFu, acc, o);

    __shared__ float s[SEGN / 32];
    if ((t & 31) == 0) s[t >> 5] = acc;
    __syncthreads();

    // Thread 0 only: accumulate into spread slots, detect last block, finalize.
    // Other threads (and other blocks) exit immediately — no extra barrier.
    if (t == 0) {
        float bs = 0.0f;
        #pragma unroll
        for (int i = 0; i < SEGN / 32; i++) bs += s[i];

        // 32 distinct L2 addresses, ~64 adds each, spread over the kernel
        // lifetime -> negligible atomic contention.
        atomicAdd(&g_slots[blockIdx.x & (NSLOTS - 1)], bs);
        __threadfence();
        unsigned int done = atomicAdd(&g_counter, 1u);

        if (done == (unsigned int)(nblocks - 1)) {
            // Last block: fold the 32 slots (32 independent loads, one
            // latency exposure) and reset state for the next graph replay.
            float v[NSLOTS];
            #pragma unroll
            for (int i = 0; i < NSLOTS; i++) v[i] = __ldcg(&g_slots[i]);

            float total = 0.0f;
            #pragma unroll
            for (int i = 0; i < NSLOTS; i++) {
                total += v[i];
                g_slots[i] = 0.0f;
            }

            // Decode scale: float32 bit pattern vs integer bit pattern.
            uint32_t u = scale_raw[0];
            float    f = __uint_as_float(u);
            float    scale;
            if (fabsf(f) >= 1e-30f && fabsf(f) < 1e30f) scale = f;
            else                                        scale = (float)(int)u;

            out[0] = total * scale / ((float)SEGN * (float)P);
            atomicExch(&g_counter, 0u);       // reset for next replay
        }
    }
}

extern "C" void kernel_launch(void* const* d_in, const int* in_sizes, int n_in,
                              void* d_out, int out_size)
{
    const float*    x     = (const float*)d_in[0];
    const uint32_t* scale = (const uint32_t*)d_in[1];
    float*          out   = (float*)d_out;

    int P       = in_sizes[0] / (N_POINTS * 2);     // 16384
    int nblocks = P / ROWS_PER_BLOCK;               // 2048

    xing_kernel<<<nblocks, SEGN>>>(x, scale, out, P, nblocks);
}

// round 12
// speedup vs baseline: 1.7196x; 1.0019x over previous
#include <cuda_runtime.h>
#include <cstdint>

// XingLoss on GB300 (sm_103a) — converged DRAM-roofline kernel (R8 composition).
//
// Fixed geometry: x_list (P=16384, N=1024, 2) float32, scale scalar.
// segn = N/4 = 256 segments per row; segment i uses points 3i..3i+3.
//
// Design (each piece measured against alternatives, R1-R11):
//  - grid 2048 x 256, 8 rows/block, 32 regs -> 8 resident blocks/SM (occ ~86%)
//  - plain stride-3 LDG.64 loads: fully line-covered, DRAM-bound at ~6.1 TB/s
//  - algebraic cut: direct = sign(cross(v1,v2)); only one rsqrt per segment
//  - barrier-free exit: thread 0 adds block sum to 1-of-32 spread L2 slots
//    (contention-free), last-arriving block folds 32 slots and finalizes.
#define N_POINTS        1024
#define SEGN            256
#define ROWS_PER_BLOCK  8
#define NSLOTS          32

__device__ float        g_slots[NSLOTS];   // zero-init at load; reset each launch
__device__ unsigned int g_counter = 0;

// Crossing term for one segment given its 4 points.
__device__ __forceinline__ float seg_term(float2 p0, float2 p1, float2 p2, float2 p3)
{
    const float v1x = p1.x - p0.x, v1y = p1.y - p0.y;
    const float v2x = p2.x - p1.x, v2y = p2.y - p1.y;
    const float v3x = p3.x - p2.x, v3y = p3.y - p2.y;

    // direct = (s12 >= 0) depends only on sign of cross(v1,v2):
    // the positive norm product cannot flip the sign.
    const float c12 = v1x * v2y - v1y * v2x;
    const float c13 = v1x * v3y - v1y * v3x;

    const float n2   = (v1x * v1x + v1y * v1y) * (v3x * v3x + v3y * v3y);
    const float sina = c13 * rsqrtf(n2);

    return (c12 >= 0.0f) ? fmaxf(-sina, 0.0f) : fmaxf(sina, 0.0f);
}

__global__ void __launch_bounds__(SEGN, 8) xing_kernel(
    const float* __restrict__ x,
    const uint32_t* __restrict__ scale_raw,
    float* __restrict__ out, int P, int nblocks)
{
    const int t = threadIdx.x;               // segment index 0..255

    // Segment t starts at point 3t within each row.
    const float2* __restrict__ base =
        reinterpret_cast<const float2*>(x)
        + (size_t)blockIdx.x * ROWS_PER_BLOCK * N_POINTS + 3 * t;

    float acc = 0.0f;

    #pragma unroll
    for (int r = 0; r < ROWS_PER_BLOCK; r++) {
        const float2* p = base + (size_t)r * N_POINTS;
        const float2 p0 = __ldg(p + 0);
        const float2 p1 = __ldg(p + 1);
        const float2 p2 = __ldg(p + 2);
        const float2 p3 = __ldg(p + 3);
        acc += seg_term(p0, p1, p2, p3);
    }

    // ---- block reduce ----
    #pragma unroll
    for (int o = 16; o > 0; o >>= 1)
        acc += __shfl_down_sync(0xFFFFFFFFu, acc, o);

    __shared__ float s[SEGN / 32];
    if ((t & 31) == 0) s[t >> 5] = acc;
    __syncthreads();

    // Thread 0 only: accumulate into spread slots, detect last block, finalize.
    // Other threads (and other blocks) exit immediately — no extra barrier.
    if (t == 0) {
        float bs = 0.0f;
        #pragma unroll
        for (int i = 0; i < SEGN / 32; i++) bs += s[i];

        // 32 distinct L2 addresses, ~64 adds each, spread over the kernel
        // lifetime -> negligible atomic contention.
        atomicAdd(&g_slots[blockIdx.x & (NSLOTS - 1)], bs);
        __threadfence();
        unsigned int done = atomicAdd(&g_counter, 1u);

        if (done == (unsigned int)(nblocks - 1)) {
            // Last block: fold the 32 slots (32 independent loads, one
            // latency exposure) and reset state for the next graph replay.
            float v[NSLOTS];
            #pragma unroll
            for (int i = 0; i < NSLOTS; i++) v[i] = __ldcg(&g_slots[i]);

            float total = 0.0f;
            #pragma unroll
            for (int i = 0; i < NSLOTS; i++) {
                total += v[i];
                g_slots[i] = 0.0f;
            }

            // Decode scale: float32 bit pattern vs integer bit pattern.
            uint32_t u = scale_raw[0];
            float    f = __uint_as_float(u);
            float    scale;
            if (fabsf(f) >= 1e-30f && fabsf(f) < 1e30f) scale = f;
            else                                        scale = (float)(int)u;

            out[0] = total * scale / ((float)SEGN * (float)P);
            atomicExch(&g_counter, 0u);       // reset for next replay
        }
    }
}

extern "C" void kernel_launch(void* const* d_in, const int* in_sizes, int n_in,
                              void* d_out, int out_size)
{
    const float*    x     = (const float*)d_in[0];
    const uint32_t* scale = (const uint32_t*)d_in[1];
    float*          out   = (float*)d_out;

    int P       = in_sizes[0] / (N_POINTS * 2);     // 16384
    int nblocks = P / ROWS_PER_BLOCK;               // 2048

    xing_kernel<<<nblocks, SEGN>>>(x, scale, out, P, nblocks);
}

// round 13
// speedup vs baseline: 1.7424x; 1.0133x over previous
#include <cuda_runtime.h>
#include <cstdint>

// XingLoss on GB300 (sm_103a). R13: R8 composition with 512-thread blocks
// (16 rows/block, grid=1024) at the same 2048-threads/SM occupancy ceiling.
//
// Fixed geometry: x_list (P=16384, N=1024, 2) float32, scale scalar.
// segn = N/4 = 256 segments per row; segment i uses points 3i..3i+3.
#define N_POINTS        1024
#define SEGN            256
#define BLOCK_THREADS   512
#define ROWS_PER_BLOCK  16
#define ROWS_PER_HALF   8          // each 256-thread half handles 8 rows
#define NSLOTS          32

__device__ float        g_slots[NSLOTS];   // zero-init at load; reset each launch
__device__ unsigned int g_counter = 0;

// Crossing term for one segment given its 4 points.
__device__ __forceinline__ float seg_term(float2 p0, float2 p1, float2 p2, float2 p3)
{
    const float v1x = p1.x - p0.x, v1y = p1.y - p0.y;
    const float v2x = p2.x - p1.x, v2y = p2.y - p1.y;
    const float v3x = p3.x - p2.x, v3y = p3.y - p2.y;

    // direct = (s12 >= 0) depends only on sign of cross(v1,v2):
    // the positive norm product cannot flip the sign.
    const float c12 = v1x * v2y - v1y * v2x;
    const float c13 = v1x * v3y - v1y * v3x;

    const float n2   = (v1x * v1x + v1y * v1y) * (v3x * v3x + v3y * v3y);
    const float sina = c13 * rsqrtf(n2);

    return (c12 >= 0.0f) ? fmaxf(-sina, 0.0f) : fmaxf(sina, 0.0f);
}

__global__ void __launch_bounds__(BLOCK_THREADS, 4) xing_kernel(
    const float* __restrict__ x,
    const uint32_t* __restrict__ scale_raw,
    float* __restrict__ out, int P, int nblocks)
{
    const int t    = threadIdx.x;            // 0..511
    const int seg  = t & (SEGN - 1);         // segment column 0..255
    const int half = t >> 8;                 // 0: rows 0-7, 1: rows 8-15

    // Segment `seg` starts at point 3*seg within each row.
    const float2* __restrict__ base =
        reinterpret_cast<const float2*>(x)
        + ((size_t)blockIdx.x * ROWS_PER_BLOCK + (size_t)half * ROWS_PER_HALF)
          * N_POINTS + 3 * seg;

    float acc = 0.0f;

    #pragma unroll
    for (int r = 0; r < ROWS_PER_HALF; r++) {
        const float2* p = base + (size_t)r * N_POINTS;
        const float2 p0 = __ldg(p + 0);
        const float2 p1 = __ldg(p + 1);
        const float2 p2 = __ldg(p + 2);
        const float2 p3 = __ldg(p + 3);
        acc += seg_term(p0, p1, p2, p3);
    }

    // ---- block reduce ----
    #pragma unroll
    for (int o = 16; o > 0; o >>= 1)
        acc += __shfl_down_sync(0xFFFFFFFFu, acc, o);

    __shared__ float s[BLOCK_THREADS / 32];
    if ((t & 31) == 0) s[t >> 5] = acc;
    __syncthreads();

    // Thread 0 only: accumulate into spread slots, detect last block, finalize.
    // Other threads (and other blocks) exit immediately — no extra barrier.
    if (t == 0) {
        float bs = 0.0f;
        #pragma unroll
        for (int i = 0; i < BLOCK_THREADS / 32; i++) bs += s[i];

        // 32 distinct L2 addresses, ~32 adds each, spread over the kernel
        // lifetime -> negligible atomic contention.
        atomicAdd(&g_slots[blockIdx.x & (NSLOTS - 1)], bs);
        __threadfence();
        unsigned int done = atomicAdd(&g_counter, 1u);

        if (done == (unsigned int)(nblocks - 1)) {
            // Last block: fold the 32 slots (32 independent loads, one
            // latency exposure) and reset state for the next graph replay.
            float v[NSLOTS];
            #pragma unroll
            for (int i = 0; i < NSLOTS; i++) v[i] = __ldcg(&g_slots[i]);

            float total = 0.0f;
            #pragma unroll
            for (int i = 0; i < NSLOTS; i++) {
                total += v[i];
                g_slots[i] = 0.0f;
            }

            // Decode scale: float32 bit pattern vs integer bit pattern.
            uint32_t u = scale_raw[0];
            float    f = __uint_as_float(u);
            float    scale;
            if (fabsf(f) >= 1e-30f && fabsf(f) < 1e30f) scale = f;
            else                                        scale = (float)(int)u;

            out[0] = total * scale / ((float)SEGN * (float)P);
            atomicExch(&g_counter, 0u);       // reset for next replay
        }
    }
}

extern "C" void kernel_launch(void* const* d_in, const int* in_sizes, int n_in,
                              void* d_out, int out_size)
{
    const float*    x     = (const float*)d_in[0];
    const uint32_t* scale = (const uint32_t*)d_in[1];
    float*          out   = (float*)d_out;

    int P       = in_sizes[0] / (N_POINTS * 2);     // 16384
    int nblocks = P / ROWS_PER_BLOCK;               // 1024

    xing_kernel<<<nblocks, BLOCK_THREADS>>>(x, scale, out, P, nblocks);
}